// round 14
// baseline (speedup 1.0000x reference)
#include <cuda_runtime.h>
#include <cuda_fp16.h>
#include <math_constants.h>
#include <cstdint>

// Problem constants (fixed shapes)
#define B_  8
#define N_  4096
#define D_  128
#define C_  256
#define K_  16
#define QW_ 2    // queries per warp in knn
#define KNN_THREADS 512
#define B_SPLIT 6   // batches 0..5 in stage 1; 6..7 in stage 2

// ---------------- scratch (device globals; allocation-free rule) -------------
__device__ float  g_M[D_ * D_];                  // WqT * Wk
__device__ float  g_v[D_];                       // bq * Wk
__device__ int    g_idx[B_ * N_ * K_];           // knn indices
__device__ float  g_qt[(size_t)B_ * N_ * D_];    // folded query (fp32)
__device__ __half g_Ft[(size_t)B_ * N_ * C_];    // transposed features [B,N,C] fp16
__device__ __half g_X16[(size_t)B_ * N_ * D_];   // concat features [B,N,D] fp16

// ---------------- K0: fold weights ------------------------------------------
__global__ void fold_kernel(const float* __restrict__ Wq,
                            const float* __restrict__ Wk,
                            const float* __restrict__ bq) {
    int c = blockIdx.x;      // 0..127
    int d = threadIdx.x;     // 0..127
    float acc = 0.f;
#pragma unroll 8
    for (int e = 0; e < D_; e++)
        acc = fmaf(Wq[e * D_ + c], Wk[e * D_ + d], acc);
    g_M[c * D_ + d] = acc;
    if (c == 0) {
        float a2 = 0.f;
#pragma unroll 8
        for (int e = 0; e < D_; e++)
            a2 = fmaf(bq[e], Wk[e * D_ + d], a2);
        g_v[d] = a2;
    }
}

// ---------------- K1: KNN, warp serves 2 queries (round-8/13 version) --------
// Bit-exact round-13 kernel; only change is the b0 batch offset (data select).
__global__ __launch_bounds__(KNN_THREADS) void knn_kernel(const float* __restrict__ xyz,
                                                          int b0) {
    extern __shared__ float4 spts[];            // [N_] (x,y,z,|p|^2) = 64KB
    const int b = b0 + blockIdx.y;
    const int tid = threadIdx.x;

    // stage points: each thread stages 8 points via 6 coalesced float4 loads
    {
        const float4* xin = (const float4*)(xyz + (size_t)b * N_ * 3);
#pragma unroll
        for (int rep = 0; rep < 2; rep++) {
            const int tt = tid + rep * KNN_THREADS;
            float4 A = xin[3 * tt + 0];
            float4 Bv = xin[3 * tt + 1];
            float4 Cv = xin[3 * tt + 2];
            float x0 = A.x,  y0 = A.y,  z0 = A.z;
            float x1 = A.w,  y1 = Bv.x, z1 = Bv.y;
            float x2 = Bv.z, y2 = Bv.w, z2 = Cv.x;
            float x3 = Cv.y, y3 = Cv.z, z3 = Cv.w;
            spts[4 * tt + 0] = make_float4(x0, y0, z0, fmaf(x0, x0, fmaf(y0, y0, z0 * z0)));
            spts[4 * tt + 1] = make_float4(x1, y1, z1, fmaf(x1, x1, fmaf(y1, y1, z1 * z1)));
            spts[4 * tt + 2] = make_float4(x2, y2, z2, fmaf(x2, x2, fmaf(y2, y2, z2 * z2)));
            spts[4 * tt + 3] = make_float4(x3, y3, z3, fmaf(x3, x3, fmaf(y3, y3, z3 * z3)));
        }
    }
    __syncthreads();

    const int lane = tid & 31, w = tid >> 5;
    const int n0 = blockIdx.x * ((KNN_THREADS / 32) * QW_) + w * QW_;

    float4 q[QW_];
#pragma unroll
    for (int qq = 0; qq < QW_; qq++) q[qq] = spts[n0 + qq];

    float a[QW_];                               // distributed ascending lists
    int   il[QW_];
    float t[QW_];

    // ---- init: per-query bitonic KV sort (ascending) of candidates 0..31 ----
    {
        float4 p = spts[lane];
#pragma unroll
        for (int qq = 0; qq < QW_; qq++) {
            float inner = fmaf(q[qq].x, p.x, fmaf(q[qq].y, p.y, q[qq].z * p.z));
            a[qq]  = fmaf(-2.f, inner, q[qq].w + p.w);
            il[qq] = lane;
#pragma unroll
            for (int k = 2; k <= 32; k <<= 1) {
#pragma unroll
                for (int j = k >> 1; j > 0; j >>= 1) {
                    float ov = __shfl_xor_sync(0xffffffffu, a[qq], j);
                    int   oi = __shfl_xor_sync(0xffffffffu, il[qq], j);
                    bool keep_min = ((lane & k) == 0) == ((lane & j) == 0);
                    bool take_own = keep_min ? (a[qq] <= ov) : (a[qq] >= ov);
                    a[qq]  = take_own ? a[qq]  : ov;
                    il[qq] = take_own ? il[qq] : oi;
                }
            }
            t[qq] = __shfl_sync(0xffffffffu, a[qq], 15);
        }
    }

    // ---- scan remaining candidates: one point load serves 2 queries ----
    for (int i = 1; i < N_ / 32; i++) {
        float4 p = spts[i * 32 + lane];
        const int ibase = i * 32;
        float d[QW_];
#pragma unroll
        for (int qq = 0; qq < QW_; qq++) {
            float inner = fmaf(q[qq].x, p.x, fmaf(q[qq].y, p.y, q[qq].z * p.z));
            d[qq] = fmaf(-2.f, inner, q[qq].w + p.w);
        }
#pragma unroll
        for (int qq = 0; qq < QW_; qq++) {
            unsigned mask = __ballot_sync(0xffffffffu, d[qq] < t[qq]);
            if (mask) {
                do {
                    const int src = __ffs(mask) - 1;
                    mask &= mask - 1;
                    const float dd = __shfl_sync(0xffffffffu, d[qq], src);
                    const int   jj = ibase + src;
                    float au = __shfl_up_sync(0xffffffffu, a[qq], 1);
                    int   iu = __shfl_up_sync(0xffffffffu, il[qq], 1);
                    if (lane == 0) au = -CUDART_INF_F;
                    const bool ins = dd < a[qq];
                    const float an = fminf(fmaxf(au, dd), a[qq]);
                    il[qq] = !ins ? il[qq] : ((au <= dd) ? jj : iu);
                    a[qq] = an;
                } while (mask);
                t[qq] = __shfl_sync(0xffffffffu, a[qq], 15);
            }
        }
    }

    if (lane < K_) {
#pragma unroll
        for (int qq = 0; qq < QW_; qq++)
            g_idx[((size_t)b * N_ + n0 + qq) * K_ + lane] = il[qq];
    }
}

// ---------------- K2: qt = X @ M + v, 2-pass, co-residable with knn ----------
// Bit-identical to round 13.
__global__ __launch_bounds__(256) void qt_kernel(const float* __restrict__ X) {
    extern __shared__ float Ms[];               // 64*128 floats = 32KB
    const int warp = threadIdx.x >> 5, lane = threadIdx.x & 31;
    const int r0 = (blockIdx.x * 8 + warp) * 4;   // 1024 blocks * 8 warps * 4 rows

    float xr[4][4];
#pragma unroll
    for (int r = 0; r < 4; r++)
#pragma unroll
        for (int t = 0; t < 4; t++)
            xr[r][t] = X[(size_t)(r0 + r) * D_ + lane + 32 * t];

    const float4* Ms4 = (const float4*)Ms;
    const float4 vinit = ((const float4*)g_v)[lane];
    float4 acc[4] = {vinit, vinit, vinit, vinit};

#pragma unroll
    for (int h = 0; h < 2; h++) {
        __syncthreads();                        // previous half fully consumed
        for (int i = threadIdx.x; i < 2048; i += 256)   // 2048 float4 = 32KB
            ((float4*)Ms)[i] = ((const float4*)g_M)[h * 2048 + i];
        __syncthreads();
#pragma unroll
        for (int th = 0; th < 2; th++) {
            const int t = 2 * h + th;           // x-chunk == M-row block, ascending
#pragma unroll 4
            for (int l = 0; l < 32; l++) {
                float4 m = Ms4[(th * 32 + l) * 32 + lane];
#pragma unroll
                for (int r = 0; r < 4; r++) {
                    float xc = __shfl_sync(0xffffffffu, xr[r][t], l);
                    acc[r].x = fmaf(xc, m.x, acc[r].x);
                    acc[r].y = fmaf(xc, m.y, acc[r].y);
                    acc[r].z = fmaf(xc, m.z, acc[r].z);
                    acc[r].w = fmaf(xc, m.w, acc[r].w);
                }
            }
        }
    }
#pragma unroll
    for (int r = 0; r < 4; r++)
        ((float4*)g_qt)[(size_t)(r0 + r) * 32 + lane] = acc[r];
}

// ---------------- K3: transpose fp4_features [B,C,N] -> [B,N,C] fp16 ---------
__global__ void transpose_kernel(const float* __restrict__ F) {
    __shared__ float t[32][33];
    const int b = blockIdx.z;
    const int n0 = blockIdx.x * 32, c0 = blockIdx.y * 32;
    const int tx = threadIdx.x, ty = threadIdx.y;
    const float* Fb = F + (size_t)b * C_ * N_;
#pragma unroll
    for (int i = 0; i < 4; i++)
        t[ty + 8 * i][tx] = Fb[(size_t)(c0 + ty + 8 * i) * N_ + n0 + tx];
    __syncthreads();
    __half* Ftb = g_Ft + (size_t)b * N_ * C_;
#pragma unroll
    for (int i = 0; i < 4; i++)
        Ftb[(size_t)(n0 + ty + 8 * i) * C_ + c0 + tx] = __float2half(t[tx][ty + 8 * i]);
}

// ---------------- K3b: X (concat features) fp32 -> fp16 ----------------------
__global__ void xhalf_kernel(const float* __restrict__ X) {
    size_t i = (size_t)blockIdx.x * blockDim.x + threadIdx.x;  // one float4 each
    float4 v = ((const float4*)X)[i];
    __half2 a = __floats2half2_rn(v.x, v.y);
    __half2 b = __floats2half2_rn(v.z, v.w);
    uint2 u;
    u.x = *(const unsigned int*)&a;
    u.y = *(const unsigned int*)&b;
    ((uint2*)g_X16)[i] = u;
}

// ---------------- K4: scores + softmax + weighted gather + coalesced out -----
// Bit-identical to round 13; only change is the b0 batch offset.
__global__ __launch_bounds__(1024) void attn_kernel(float* __restrict__ out, int b0) {
    __shared__ float tile[32 * 258];            // [point][channel], pad 258

    const int w = threadIdx.x >> 5, lane = threadIdx.x & 31;
    const int b = b0 + blockIdx.y;
    const int n0 = blockIdx.x * 32;
    const int n = n0 + w;
    const size_t pt = (size_t)b * N_ + n;

    const float4 q = ((const float4*)g_qt)[pt * 32 + lane];    // ch 4L..4L+3
    int jlane = (lane < K_) ? g_idx[pt * K_ + lane] : 0;

    // scores: s_k = qt . X16[j_k]  (row = 128 half = 32 uint2)
    const uint2* Xv = (const uint2*)g_X16 + (size_t)b * N_ * 32;
    float s[K_];
#pragma unroll
    for (int k = 0; k < K_; k++) {
        int j = __shfl_sync(0xffffffffu, jlane, k);
        uint2 xv = Xv[(size_t)j * 32 + lane];
        float2 f0 = __half22float2(*(const __half2*)&xv.x);
        float2 f1 = __half22float2(*(const __half2*)&xv.y);
        float p = fmaf(q.x, f0.x, fmaf(q.y, f0.y, fmaf(q.z, f1.x, q.w * f1.y)));
#pragma unroll
        for (int off = 16; off > 0; off >>= 1)
            p += __shfl_xor_sync(0xffffffffu, p, off);
        s[k] = p;
    }

    const float scale = 0.08838834764831845f;   // 1/sqrt(128)
    float m = s[0] * scale;
#pragma unroll
    for (int k = 1; k < K_; k++) m = fmaxf(m, s[k] * scale);
    float sum = 0.f;
#pragma unroll
    for (int k = 0; k < K_; k++) {
        s[k] = __expf(fmaf(s[k], scale, -m));
        sum += s[k];
    }
    const float inv = 1.f / sum;

    // weighted feature gather: Ft16 row = 256 half = 32 uint4; lane ch 8L..8L+7
    float a[8] = {0.f, 0.f, 0.f, 0.f, 0.f, 0.f, 0.f, 0.f};
    const uint4* Fv = (const uint4*)g_Ft + (size_t)b * N_ * 32;
#pragma unroll
    for (int k = 0; k < K_; k++) {
        int j = __shfl_sync(0xffffffffu, jlane, k);
        float ak = s[k] * inv;
        uint4 f = Fv[(size_t)j * 32 + lane];
        float2 p0 = __half22float2(*(const __half2*)&f.x);
        float2 p1 = __half22float2(*(const __half2*)&f.y);
        float2 p2 = __half22float2(*(const __half2*)&f.z);
        float2 p3 = __half22float2(*(const __half2*)&f.w);
        a[0] = fmaf(ak, p0.x, a[0]); a[1] = fmaf(ak, p0.y, a[1]);
        a[2] = fmaf(ak, p1.x, a[2]); a[3] = fmaf(ak, p1.y, a[3]);
        a[4] = fmaf(ak, p2.x, a[4]); a[5] = fmaf(ak, p2.y, a[5]);
        a[6] = fmaf(ak, p3.x, a[6]); a[7] = fmaf(ak, p3.y, a[7]);
    }

    // stage [point][channel]; float2 stores, reads are 2-way-conflict max
    float* trow = &tile[w * 258 + 8 * lane];
#pragma unroll
    for (int i = 0; i < 4; i++)
        ((float2*)trow)[i] = make_float2(a[2 * i], a[2 * i + 1]);
    __syncthreads();

    // coalesced write: lanes sweep n, rows sweep c
    float* ob = out + (size_t)b * C_ * N_;
#pragma unroll
    for (int r = 0; r < 8; r++) {
        int c = w + r * 32;
        ob[(size_t)c * N_ + n0 + lane] = tile[lane * 258 + c];
    }
}

// ---------------- launch: batch-pipelined DAG --------------------------------
//  s0: knn1(b0..5) --e1--> knn2(b6..7) --(wait evJ)--> attn2(b6..7) --(wait e2)
//  s2: prep(fold,transpose,xhalf,qt) --evJ--> (wait e1) attn1(b0..5) --e2
// attn1 runs concurrently with knn2; only attn2 (~15-20us) stays exposed.
extern "C" void kernel_launch(void* const* d_in, const int* in_sizes, int n_in,
                              void* d_out, int out_size) {
    (void)in_sizes; (void)n_in; (void)out_size;
    const float* xyz = (const float*)d_in[0];   // [B,N,3]
    const float* F   = (const float*)d_in[1];   // [B,C,N]
    const float* X   = (const float*)d_in[2];   // [B,N,D]
    const float* Wq  = (const float*)d_in[3];
    const float* bq  = (const float*)d_in[4];
    const float* Wk  = (const float*)d_in[5];
    float* out = (float*)d_out;                 // [B,C,N]

    // One-time host-side handles (no device memory; identical work every call).
    static cudaStream_t s2 = nullptr;
    static cudaEvent_t evF = nullptr, evJ = nullptr, e1 = nullptr, e2 = nullptr;
    if (s2 == nullptr) {
        cudaStreamCreateWithFlags(&s2, cudaStreamNonBlocking);
        cudaEventCreateWithFlags(&evF, cudaEventDisableTiming);
        cudaEventCreateWithFlags(&evJ, cudaEventDisableTiming);
        cudaEventCreateWithFlags(&e1,  cudaEventDisableTiming);
        cudaEventCreateWithFlags(&e2,  cudaEventDisableTiming);
        cudaFuncSetAttribute(knn_kernel, cudaFuncAttributeMaxDynamicSharedMemorySize, 65536);
    }

    // Fork: side stream s2 joins the (possibly capturing) main stream.
    cudaEventRecord(evF, 0);
    cudaStreamWaitEvent(s2, evF, 0);

    // Main-stream: knn stage 1 (batches 0..5), then stage 2 (batches 6..7).
    knn_kernel<<<dim3(N_ / ((KNN_THREADS / 32) * QW_), B_SPLIT), KNN_THREADS, 65536, 0>>>(xyz, 0);
    cudaEventRecord(e1, 0);
    knn_kernel<<<dim3(N_ / ((KNN_THREADS / 32) * QW_), B_ - B_SPLIT), KNN_THREADS, 65536, 0>>>(xyz, B_SPLIT);

    // Side-stream: prep chain (hidden under knn1)
    fold_kernel<<<D_, D_, 0, s2>>>(Wq, Wk, bq);
    transpose_kernel<<<dim3(N_ / 32, C_ / 32, B_), dim3(32, 8), 0, s2>>>(F);
    xhalf_kernel<<<(B_ * N_ * D_ / 4) / 256, 256, 0, s2>>>(X);
    qt_kernel<<<(B_ * N_) / 32, 256, 32768, s2>>>(X);
    cudaEventRecord(evJ, s2);

    // Side-stream: attn stage 1 as soon as knn1 is done (overlaps knn2)
    cudaStreamWaitEvent(s2, e1, 0);
    attn_kernel<<<dim3(N_ / 32, B_SPLIT), 1024, 0, s2>>>(out, 0);
    cudaEventRecord(e2, s2);

    // Main-stream: attn stage 2 after knn2 (+ qt ready), then join s2.
    cudaStreamWaitEvent(0, evJ, 0);
    attn_kernel<<<dim3(N_ / 32, B_ - B_SPLIT), 1024, 0, 0>>>(out, B_SPLIT);
    cudaStreamWaitEvent(0, e2, 0);
}

// round 15
// speedup vs baseline: 1.0664x; 1.0664x over previous
#include <cuda_runtime.h>
#include <cuda_fp16.h>
#include <math_constants.h>
#include <cstdint>

// Problem constants (fixed shapes)
#define B_  8
#define N_  4096
#define D_  128
#define C_  256
#define K_  16
#define QW_ 2    // queries per warp in knn
#define KNN_THREADS 512

// ---------------- scratch (device globals; allocation-free rule) -------------
__device__ float  g_M[D_ * D_];                  // WqT * Wk
__device__ float  g_v[D_];                       // bq * Wk
__device__ int    g_idx[B_ * N_ * K_];           // knn indices
__device__ float  g_qt[(size_t)B_ * N_ * D_];    // folded query (fp32)
__device__ __half g_Ft[(size_t)B_ * N_ * C_];    // transposed features [B,N,C] fp16
__device__ __half g_X16[(size_t)B_ * N_ * D_];   // concat features [B,N,D] fp16

// ---------------- K0: fold weights ------------------------------------------
__global__ void fold_kernel(const float* __restrict__ Wq,
                            const float* __restrict__ Wk,
                            const float* __restrict__ bq) {
    int c = blockIdx.x;      // 0..127
    int d = threadIdx.x;     // 0..127
    float acc = 0.f;
#pragma unroll 8
    for (int e = 0; e < D_; e++)
        acc = fmaf(Wq[e * D_ + c], Wk[e * D_ + d], acc);
    g_M[c * D_ + d] = acc;
    if (c == 0) {
        float a2 = 0.f;
#pragma unroll 8
        for (int e = 0; e < D_; e++)
            a2 = fmaf(bq[e], Wk[e * D_ + d], a2);
        g_v[d] = a2;
    }
}

// ---------------- K1: KNN, warp serves 2 queries (round-13 + unroll 2) -------
// Bit-exact round-13 selection: d2 = fmaf(-2, q.p, |q|^2+|p|^2); 32-entry
// (d2,idx) distributed sorted list; bitonic-KV init on candidates 0..31;
// one 32-wide ballot per iteration per query; stale-threshold warp insert;
// lanes 0..15 emitted. Only change: unroll 2 on the scan loop (sequential
// iterations in program order -> identical candidate order -> identical output).
__global__ __launch_bounds__(KNN_THREADS) void knn_kernel(const float* __restrict__ xyz) {
    extern __shared__ float4 spts[];            // [N_] (x,y,z,|p|^2) = 64KB
    const int b = blockIdx.y;
    const int tid = threadIdx.x;

    // stage points: each thread stages 8 points via 6 coalesced float4 loads
    {
        const float4* xin = (const float4*)(xyz + (size_t)b * N_ * 3);
#pragma unroll
        for (int rep = 0; rep < 2; rep++) {
            const int tt = tid + rep * KNN_THREADS;
            float4 A = xin[3 * tt + 0];
            float4 Bv = xin[3 * tt + 1];
            float4 Cv = xin[3 * tt + 2];
            float x0 = A.x,  y0 = A.y,  z0 = A.z;
            float x1 = A.w,  y1 = Bv.x, z1 = Bv.y;
            float x2 = Bv.z, y2 = Bv.w, z2 = Cv.x;
            float x3 = Cv.y, y3 = Cv.z, z3 = Cv.w;
            spts[4 * tt + 0] = make_float4(x0, y0, z0, fmaf(x0, x0, fmaf(y0, y0, z0 * z0)));
            spts[4 * tt + 1] = make_float4(x1, y1, z1, fmaf(x1, x1, fmaf(y1, y1, z1 * z1)));
            spts[4 * tt + 2] = make_float4(x2, y2, z2, fmaf(x2, x2, fmaf(y2, y2, z2 * z2)));
            spts[4 * tt + 3] = make_float4(x3, y3, z3, fmaf(x3, x3, fmaf(y3, y3, z3 * z3)));
        }
    }
    __syncthreads();

    const int lane = tid & 31, w = tid >> 5;
    const int n0 = blockIdx.x * ((KNN_THREADS / 32) * QW_) + w * QW_;

    float4 q[QW_];
#pragma unroll
    for (int qq = 0; qq < QW_; qq++) q[qq] = spts[n0 + qq];

    float a[QW_];                               // distributed ascending lists
    int   il[QW_];
    float t[QW_];

    // ---- init: per-query bitonic KV sort (ascending) of candidates 0..31 ----
    {
        float4 p = spts[lane];
#pragma unroll
        for (int qq = 0; qq < QW_; qq++) {
            float inner = fmaf(q[qq].x, p.x, fmaf(q[qq].y, p.y, q[qq].z * p.z));
            a[qq]  = fmaf(-2.f, inner, q[qq].w + p.w);
            il[qq] = lane;
#pragma unroll
            for (int k = 2; k <= 32; k <<= 1) {
#pragma unroll
                for (int j = k >> 1; j > 0; j >>= 1) {
                    float ov = __shfl_xor_sync(0xffffffffu, a[qq], j);
                    int   oi = __shfl_xor_sync(0xffffffffu, il[qq], j);
                    bool keep_min = ((lane & k) == 0) == ((lane & j) == 0);
                    bool take_own = keep_min ? (a[qq] <= ov) : (a[qq] >= ov);
                    a[qq]  = take_own ? a[qq]  : ov;
                    il[qq] = take_own ? il[qq] : oi;
                }
            }
            t[qq] = __shfl_sync(0xffffffffu, a[qq], 15);
        }
    }

    // ---- scan remaining candidates: one point load serves 2 queries ----
#pragma unroll 2
    for (int i = 1; i < N_ / 32; i++) {
        float4 p = spts[i * 32 + lane];
        const int ibase = i * 32;
        float d[QW_];
#pragma unroll
        for (int qq = 0; qq < QW_; qq++) {
            float inner = fmaf(q[qq].x, p.x, fmaf(q[qq].y, p.y, q[qq].z * p.z));
            d[qq] = fmaf(-2.f, inner, q[qq].w + p.w);
        }
#pragma unroll
        for (int qq = 0; qq < QW_; qq++) {
            unsigned mask = __ballot_sync(0xffffffffu, d[qq] < t[qq]);
            if (mask) {
                do {
                    const int src = __ffs(mask) - 1;
                    mask &= mask - 1;
                    const float dd = __shfl_sync(0xffffffffu, d[qq], src);
                    const int   jj = ibase + src;
                    float au = __shfl_up_sync(0xffffffffu, a[qq], 1);
                    int   iu = __shfl_up_sync(0xffffffffu, il[qq], 1);
                    if (lane == 0) au = -CUDART_INF_F;
                    const bool ins = dd < a[qq];
                    const float an = fminf(fmaxf(au, dd), a[qq]);
                    il[qq] = !ins ? il[qq] : ((au <= dd) ? jj : iu);
                    a[qq] = an;
                } while (mask);
                t[qq] = __shfl_sync(0xffffffffu, a[qq], 15);
            }
        }
    }

    if (lane < K_) {
#pragma unroll
        for (int qq = 0; qq < QW_; qq++)
            g_idx[((size_t)b * N_ + n0 + qq) * K_ + lane] = il[qq];
    }
}

// ---------------- K2: qt = X @ M + v, 2-pass, co-residable with knn ----------
// Bit-identical to round 13.
__global__ __launch_bounds__(256) void qt_kernel(const float* __restrict__ X) {
    extern __shared__ float Ms[];               // 64*128 floats = 32KB
    const int warp = threadIdx.x >> 5, lane = threadIdx.x & 31;
    const int r0 = (blockIdx.x * 8 + warp) * 4;   // 1024 blocks * 8 warps * 4 rows

    float xr[4][4];
#pragma unroll
    for (int r = 0; r < 4; r++)
#pragma unroll
        for (int t = 0; t < 4; t++)
            xr[r][t] = X[(size_t)(r0 + r) * D_ + lane + 32 * t];

    const float4* Ms4 = (const float4*)Ms;
    const float4 vinit = ((const float4*)g_v)[lane];
    float4 acc[4] = {vinit, vinit, vinit, vinit};

#pragma unroll
    for (int h = 0; h < 2; h++) {
        __syncthreads();                        // previous half fully consumed
        for (int i = threadIdx.x; i < 2048; i += 256)   // 2048 float4 = 32KB
            ((float4*)Ms)[i] = ((const float4*)g_M)[h * 2048 + i];
        __syncthreads();
#pragma unroll
        for (int th = 0; th < 2; th++) {
            const int t = 2 * h + th;           // x-chunk == M-row block, ascending
#pragma unroll 4
            for (int l = 0; l < 32; l++) {
                float4 m = Ms4[(th * 32 + l) * 32 + lane];
#pragma unroll
                for (int r = 0; r < 4; r++) {
                    float xc = __shfl_sync(0xffffffffu, xr[r][t], l);
                    acc[r].x = fmaf(xc, m.x, acc[r].x);
                    acc[r].y = fmaf(xc, m.y, acc[r].y);
                    acc[r].z = fmaf(xc, m.z, acc[r].z);
                    acc[r].w = fmaf(xc, m.w, acc[r].w);
                }
            }
        }
    }
#pragma unroll
    for (int r = 0; r < 4; r++)
        ((float4*)g_qt)[(size_t)(r0 + r) * 32 + lane] = acc[r];
}

// ---------------- K3: transpose fp4_features [B,C,N] -> [B,N,C] fp16 ---------
__global__ void transpose_kernel(const float* __restrict__ F) {
    __shared__ float t[32][33];
    const int b = blockIdx.z;
    const int n0 = blockIdx.x * 32, c0 = blockIdx.y * 32;
    const int tx = threadIdx.x, ty = threadIdx.y;
    const float* Fb = F + (size_t)b * C_ * N_;
#pragma unroll
    for (int i = 0; i < 4; i++)
        t[ty + 8 * i][tx] = Fb[(size_t)(c0 + ty + 8 * i) * N_ + n0 + tx];
    __syncthreads();
    __half* Ftb = g_Ft + (size_t)b * N_ * C_;
#pragma unroll
    for (int i = 0; i < 4; i++)
        Ftb[(size_t)(n0 + ty + 8 * i) * C_ + c0 + tx] = __float2half(t[tx][ty + 8 * i]);
}

// ---------------- K3b: X (concat features) fp32 -> fp16 ----------------------
__global__ void xhalf_kernel(const float* __restrict__ X) {
    size_t i = (size_t)blockIdx.x * blockDim.x + threadIdx.x;  // one float4 each
    float4 v = ((const float4*)X)[i];
    __half2 a = __floats2half2_rn(v.x, v.y);
    __half2 b = __floats2half2_rn(v.z, v.w);
    uint2 u;
    u.x = *(const unsigned int*)&a;
    u.y = *(const unsigned int*)&b;
    ((uint2*)g_X16)[i] = u;
}

// ---------------- K4: scores + softmax + weighted gather + coalesced out -----
// Bit-identical to round 13.
__global__ __launch_bounds__(1024) void attn_kernel(float* __restrict__ out) {
    __shared__ float tile[32 * 258];            // [point][channel], pad 258

    const int w = threadIdx.x >> 5, lane = threadIdx.x & 31;
    const int b = blockIdx.y;
    const int n0 = blockIdx.x * 32;
    const int n = n0 + w;
    const size_t pt = (size_t)b * N_ + n;

    const float4 q = ((const float4*)g_qt)[pt * 32 + lane];    // ch 4L..4L+3
    int jlane = (lane < K_) ? g_idx[pt * K_ + lane] : 0;

    // scores: s_k = qt . X16[j_k]  (row = 128 half = 32 uint2)
    const uint2* Xv = (const uint2*)g_X16 + (size_t)b * N_ * 32;
    float s[K_];
#pragma unroll
    for (int k = 0; k < K_; k++) {
        int j = __shfl_sync(0xffffffffu, jlane, k);
        uint2 xv = Xv[(size_t)j * 32 + lane];
        float2 f0 = __half22float2(*(const __half2*)&xv.x);
        float2 f1 = __half22float2(*(const __half2*)&xv.y);
        float p = fmaf(q.x, f0.x, fmaf(q.y, f0.y, fmaf(q.z, f1.x, q.w * f1.y)));
#pragma unroll
        for (int off = 16; off > 0; off >>= 1)
            p += __shfl_xor_sync(0xffffffffu, p, off);
        s[k] = p;
    }

    const float scale = 0.08838834764831845f;   // 1/sqrt(128)
    float m = s[0] * scale;
#pragma unroll
    for (int k = 1; k < K_; k++) m = fmaxf(m, s[k] * scale);
    float sum = 0.f;
#pragma unroll
    for (int k = 0; k < K_; k++) {
        s[k] = __expf(fmaf(s[k], scale, -m));
        sum += s[k];
    }
    const float inv = 1.f / sum;

    // weighted feature gather: Ft16 row = 256 half = 32 uint4; lane ch 8L..8L+7
    float a[8] = {0.f, 0.f, 0.f, 0.f, 0.f, 0.f, 0.f, 0.f};
    const uint4* Fv = (const uint4*)g_Ft + (size_t)b * N_ * 32;
#pragma unroll
    for (int k = 0; k < K_; k++) {
        int j = __shfl_sync(0xffffffffu, jlane, k);
        float ak = s[k] * inv;
        uint4 f = Fv[(size_t)j * 32 + lane];
        float2 p0 = __half22float2(*(const __half2*)&f.x);
        float2 p1 = __half22float2(*(const __half2*)&f.y);
        float2 p2 = __half22float2(*(const __half2*)&f.z);
        float2 p3 = __half22float2(*(const __half2*)&f.w);
        a[0] = fmaf(ak, p0.x, a[0]); a[1] = fmaf(ak, p0.y, a[1]);
        a[2] = fmaf(ak, p1.x, a[2]); a[3] = fmaf(ak, p1.y, a[3]);
        a[4] = fmaf(ak, p2.x, a[4]); a[5] = fmaf(ak, p2.y, a[5]);
        a[6] = fmaf(ak, p3.x, a[6]); a[7] = fmaf(ak, p3.y, a[7]);
    }

    // stage [point][channel]; float2 stores, reads are 2-way-conflict max
    float* trow = &tile[w * 258 + 8 * lane];
#pragma unroll
    for (int i = 0; i < 4; i++)
        ((float2*)trow)[i] = make_float2(a[2 * i], a[2 * i + 1]);
    __syncthreads();

    // coalesced write: lanes sweep n, rows sweep c
    float* ob = out + (size_t)b * C_ * N_;
#pragma unroll
    for (int r = 0; r < 8; r++) {
        int c = w + r * 32;
        ob[(size_t)c * N_ + n0 + lane] = tile[lane * 258 + c];
    }
}

// ---------------- launch: forked graph (knn || prep), join before attn -------
extern "C" void kernel_launch(void* const* d_in, const int* in_sizes, int n_in,
                              void* d_out, int out_size) {
    (void)in_sizes; (void)n_in; (void)out_size;
    const float* xyz = (const float*)d_in[0];   // [B,N,3]
    const float* F   = (const float*)d_in[1];   // [B,C,N]
    const float* X   = (const float*)d_in[2];   // [B,N,D]
    const float* Wq  = (const float*)d_in[3];
    const float* bq  = (const float*)d_in[4];
    const float* Wk  = (const float*)d_in[5];
    float* out = (float*)d_out;                 // [B,C,N]

    // One-time host-side handles (no device memory; identical work every call).
    static cudaStream_t s2 = nullptr;
    static cudaEvent_t evF = nullptr, evJ = nullptr;
    if (s2 == nullptr) {
        cudaStreamCreateWithFlags(&s2, cudaStreamNonBlocking);
        cudaEventCreateWithFlags(&evF, cudaEventDisableTiming);
        cudaEventCreateWithFlags(&evJ, cudaEventDisableTiming);
        cudaFuncSetAttribute(knn_kernel, cudaFuncAttributeMaxDynamicSharedMemorySize, 65536);
    }

    // Fork: side stream s2 joins the (possibly capturing) main stream.
    cudaEventRecord(evF, 0);
    cudaStreamWaitEvent(s2, evF, 0);

    // Main-stream branch: knn (critical path, ~134us)
    knn_kernel<<<dim3(N_ / ((KNN_THREADS / 32) * QW_), B_), KNN_THREADS, 65536, 0>>>(xyz);

    // Side-stream branch: prep chain; qt co-resides with knn
    fold_kernel<<<D_, D_, 0, s2>>>(Wq, Wk, bq);
    transpose_kernel<<<dim3(N_ / 32, C_ / 32, B_), dim3(32, 8), 0, s2>>>(F);
    xhalf_kernel<<<(B_ * N_ * D_ / 4) / 256, 256, 0, s2>>>(X);
    qt_kernel<<<(B_ * N_) / 32, 256, 32768, s2>>>(X);

    // Join, then attention epilogue on the main stream.
    cudaEventRecord(evJ, s2);
    cudaStreamWaitEvent(0, evJ, 0);
    attn_kernel<<<dim3(N_ / 32, B_), 1024, 0, 0>>>(out);
}

// round 16
// speedup vs baseline: 1.0784x; 1.0112x over previous
#include <cuda_runtime.h>
#include <cuda_fp16.h>
#include <math_constants.h>
#include <cstdint>

// Problem constants (fixed shapes)
#define B_  8
#define N_  4096
#define D_  128
#define C_  256
#define K_  16
#define QW_ 2    // queries per warp in knn
#define KNN_THREADS 512

// ---------------- scratch (device globals; allocation-free rule) -------------
__device__ float  g_M[D_ * D_];                  // WqT * Wk
__device__ float  g_v[D_];                       // bq * Wk
__device__ int    g_idx[B_ * N_ * K_];           // knn indices
__device__ float  g_qt[(size_t)B_ * N_ * D_];    // folded query (fp32)
__device__ __half g_Ft[(size_t)B_ * N_ * C_];    // transposed features [B,N,C] fp16
__device__ __half g_X16[(size_t)B_ * N_ * D_];   // concat features [B,N,D] fp16

// ---------------- K0: fold weights ------------------------------------------
__global__ void fold_kernel(const float* __restrict__ Wq,
                            const float* __restrict__ Wk,
                            const float* __restrict__ bq) {
    int c = blockIdx.x;      // 0..127
    int d = threadIdx.x;     // 0..127
    float acc = 0.f;
#pragma unroll 8
    for (int e = 0; e < D_; e++)
        acc = fmaf(Wq[e * D_ + c], Wk[e * D_ + d], acc);
    g_M[c * D_ + d] = acc;
    if (c == 0) {
        float a2 = 0.f;
#pragma unroll 8
        for (int e = 0; e < D_; e++)
            a2 = fmaf(bq[e], Wk[e * D_ + d], a2);
        g_v[d] = a2;
    }
}

// ---------------- K1: KNN, warp serves 2 queries (round-15 + unroll 4) -------
// Bit-exact round-13/15 selection: d2 = fmaf(-2, q.p, |q|^2+|p|^2); 32-entry
// (d2,idx) distributed sorted list; bitonic-KV init on candidates 0..31;
// one 32-wide ballot per iteration per query; stale-threshold warp insert;
// lanes 0..15 emitted. Changes vs round 15: scan unroll 2 -> 4, and
// __launch_bounds__(512, 3) pins 3 resident blocks/SM (regs clamped <= 42)
// so the deeper unroll cannot fall off the residency cliff (round-7 lesson).
__global__ __launch_bounds__(KNN_THREADS, 3) void knn_kernel(const float* __restrict__ xyz) {
    extern __shared__ float4 spts[];            // [N_] (x,y,z,|p|^2) = 64KB
    const int b = blockIdx.y;
    const int tid = threadIdx.x;

    // stage points: each thread stages 8 points via 6 coalesced float4 loads
    {
        const float4* xin = (const float4*)(xyz + (size_t)b * N_ * 3);
#pragma unroll
        for (int rep = 0; rep < 2; rep++) {
            const int tt = tid + rep * KNN_THREADS;
            float4 A = xin[3 * tt + 0];
            float4 Bv = xin[3 * tt + 1];
            float4 Cv = xin[3 * tt + 2];
            float x0 = A.x,  y0 = A.y,  z0 = A.z;
            float x1 = A.w,  y1 = Bv.x, z1 = Bv.y;
            float x2 = Bv.z, y2 = Bv.w, z2 = Cv.x;
            float x3 = Cv.y, y3 = Cv.z, z3 = Cv.w;
            spts[4 * tt + 0] = make_float4(x0, y0, z0, fmaf(x0, x0, fmaf(y0, y0, z0 * z0)));
            spts[4 * tt + 1] = make_float4(x1, y1, z1, fmaf(x1, x1, fmaf(y1, y1, z1 * z1)));
            spts[4 * tt + 2] = make_float4(x2, y2, z2, fmaf(x2, x2, fmaf(y2, y2, z2 * z2)));
            spts[4 * tt + 3] = make_float4(x3, y3, z3, fmaf(x3, x3, fmaf(y3, y3, z3 * z3)));
        }
    }
    __syncthreads();

    const int lane = tid & 31, w = tid >> 5;
    const int n0 = blockIdx.x * ((KNN_THREADS / 32) * QW_) + w * QW_;

    float4 q[QW_];
#pragma unroll
    for (int qq = 0; qq < QW_; qq++) q[qq] = spts[n0 + qq];

    float a[QW_];                               // distributed ascending lists
    int   il[QW_];
    float t[QW_];

    // ---- init: per-query bitonic KV sort (ascending) of candidates 0..31 ----
    {
        float4 p = spts[lane];
#pragma unroll
        for (int qq = 0; qq < QW_; qq++) {
            float inner = fmaf(q[qq].x, p.x, fmaf(q[qq].y, p.y, q[qq].z * p.z));
            a[qq]  = fmaf(-2.f, inner, q[qq].w + p.w);
            il[qq] = lane;
#pragma unroll
            for (int k = 2; k <= 32; k <<= 1) {
#pragma unroll
                for (int j = k >> 1; j > 0; j >>= 1) {
                    float ov = __shfl_xor_sync(0xffffffffu, a[qq], j);
                    int   oi = __shfl_xor_sync(0xffffffffu, il[qq], j);
                    bool keep_min = ((lane & k) == 0) == ((lane & j) == 0);
                    bool take_own = keep_min ? (a[qq] <= ov) : (a[qq] >= ov);
                    a[qq]  = take_own ? a[qq]  : ov;
                    il[qq] = take_own ? il[qq] : oi;
                }
            }
            t[qq] = __shfl_sync(0xffffffffu, a[qq], 15);
        }
    }

    // ---- scan remaining candidates: one point load serves 2 queries ----
#pragma unroll 4
    for (int i = 1; i < N_ / 32; i++) {
        float4 p = spts[i * 32 + lane];
        const int ibase = i * 32;
        float d[QW_];
#pragma unroll
        for (int qq = 0; qq < QW_; qq++) {
            float inner = fmaf(q[qq].x, p.x, fmaf(q[qq].y, p.y, q[qq].z * p.z));
            d[qq] = fmaf(-2.f, inner, q[qq].w + p.w);
        }
#pragma unroll
        for (int qq = 0; qq < QW_; qq++) {
            unsigned mask = __ballot_sync(0xffffffffu, d[qq] < t[qq]);
            if (mask) {
                do {
                    const int src = __ffs(mask) - 1;
                    mask &= mask - 1;
                    const float dd = __shfl_sync(0xffffffffu, d[qq], src);
                    const int   jj = ibase + src;
                    float au = __shfl_up_sync(0xffffffffu, a[qq], 1);
                    int   iu = __shfl_up_sync(0xffffffffu, il[qq], 1);
                    if (lane == 0) au = -CUDART_INF_F;
                    const bool ins = dd < a[qq];
                    const float an = fminf(fmaxf(au, dd), a[qq]);
                    il[qq] = !ins ? il[qq] : ((au <= dd) ? jj : iu);
                    a[qq] = an;
                } while (mask);
                t[qq] = __shfl_sync(0xffffffffu, a[qq], 15);
            }
        }
    }

    if (lane < K_) {
#pragma unroll
        for (int qq = 0; qq < QW_; qq++)
            g_idx[((size_t)b * N_ + n0 + qq) * K_ + lane] = il[qq];
    }
}

// ---------------- K2: qt = X @ M + v, 2-pass, co-residable with knn ----------
// Bit-identical to round 13/15.
__global__ __launch_bounds__(256) void qt_kernel(const float* __restrict__ X) {
    extern __shared__ float Ms[];               // 64*128 floats = 32KB
    const int warp = threadIdx.x >> 5, lane = threadIdx.x & 31;
    const int r0 = (blockIdx.x * 8 + warp) * 4;   // 1024 blocks * 8 warps * 4 rows

    float xr[4][4];
#pragma unroll
    for (int r = 0; r < 4; r++)
#pragma unroll
        for (int t = 0; t < 4; t++)
            xr[r][t] = X[(size_t)(r0 + r) * D_ + lane + 32 * t];

    const float4* Ms4 = (const float4*)Ms;
    const float4 vinit = ((const float4*)g_v)[lane];
    float4 acc[4] = {vinit, vinit, vinit, vinit};

#pragma unroll
    for (int h = 0; h < 2; h++) {
        __syncthreads();                        // previous half fully consumed
        for (int i = threadIdx.x; i < 2048; i += 256)   // 2048 float4 = 32KB
            ((float4*)Ms)[i] = ((const float4*)g_M)[h * 2048 + i];
        __syncthreads();
#pragma unroll
        for (int th = 0; th < 2; th++) {
            const int t = 2 * h + th;           // x-chunk == M-row block, ascending
#pragma unroll 4
            for (int l = 0; l < 32; l++) {
                float4 m = Ms4[(th * 32 + l) * 32 + lane];
#pragma unroll
                for (int r = 0; r < 4; r++) {
                    float xc = __shfl_sync(0xffffffffu, xr[r][t], l);
                    acc[r].x = fmaf(xc, m.x, acc[r].x);
                    acc[r].y = fmaf(xc, m.y, acc[r].y);
                    acc[r].z = fmaf(xc, m.z, acc[r].z);
                    acc[r].w = fmaf(xc, m.w, acc[r].w);
                }
            }
        }
    }
#pragma unroll
    for (int r = 0; r < 4; r++)
        ((float4*)g_qt)[(size_t)(r0 + r) * 32 + lane] = acc[r];
}

// ---------------- K3: transpose fp4_features [B,C,N] -> [B,N,C] fp16 ---------
__global__ void transpose_kernel(const float* __restrict__ F) {
    __shared__ float t[32][33];
    const int b = blockIdx.z;
    const int n0 = blockIdx.x * 32, c0 = blockIdx.y * 32;
    const int tx = threadIdx.x, ty = threadIdx.y;
    const float* Fb = F + (size_t)b * C_ * N_;
#pragma unroll
    for (int i = 0; i < 4; i++)
        t[ty + 8 * i][tx] = Fb[(size_t)(c0 + ty + 8 * i) * N_ + n0 + tx];
    __syncthreads();
    __half* Ftb = g_Ft + (size_t)b * N_ * C_;
#pragma unroll
    for (int i = 0; i < 4; i++)
        Ftb[(size_t)(n0 + ty + 8 * i) * C_ + c0 + tx] = __float2half(t[tx][ty + 8 * i]);
}

// ---------------- K3b: X (concat features) fp32 -> fp16 ----------------------
__global__ void xhalf_kernel(const float* __restrict__ X) {
    size_t i = (size_t)blockIdx.x * blockDim.x + threadIdx.x;  // one float4 each
    float4 v = ((const float4*)X)[i];
    __half2 a = __floats2half2_rn(v.x, v.y);
    __half2 b = __floats2half2_rn(v.z, v.w);
    uint2 u;
    u.x = *(const unsigned int*)&a;
    u.y = *(const unsigned int*)&b;
    ((uint2*)g_X16)[i] = u;
}

// ---------------- K4: scores + softmax + weighted gather + coalesced out -----
// Bit-identical to round 13/15.
__global__ __launch_bounds__(1024) void attn_kernel(float* __restrict__ out) {
    __shared__ float tile[32 * 258];            // [point][channel], pad 258

    const int w = threadIdx.x >> 5, lane = threadIdx.x & 31;
    const int b = blockIdx.y;
    const int n0 = blockIdx.x * 32;
    const int n = n0 + w;
    const size_t pt = (size_t)b * N_ + n;

    const float4 q = ((const float4*)g_qt)[pt * 32 + lane];    // ch 4L..4L+3
    int jlane = (lane < K_) ? g_idx[pt * K_ + lane] : 0;

    // scores: s_k = qt . X16[j_k]  (row = 128 half = 32 uint2)
    const uint2* Xv = (const uint2*)g_X16 + (size_t)b * N_ * 32;
    float s[K_];
#pragma unroll
    for (int k = 0; k < K_; k++) {
        int j = __shfl_sync(0xffffffffu, jlane, k);
        uint2 xv = Xv[(size_t)j * 32 + lane];
        float2 f0 = __half22float2(*(const __half2*)&xv.x);
        float2 f1 = __half22float2(*(const __half2*)&xv.y);
        float p = fmaf(q.x, f0.x, fmaf(q.y, f0.y, fmaf(q.z, f1.x, q.w * f1.y)));
#pragma unroll
        for (int off = 16; off > 0; off >>= 1)
            p += __shfl_xor_sync(0xffffffffu, p, off);
        s[k] = p;
    }

    const float scale = 0.08838834764831845f;   // 1/sqrt(128)
    float m = s[0] * scale;
#pragma unroll
    for (int k = 1; k < K_; k++) m = fmaxf(m, s[k] * scale);
    float sum = 0.f;
#pragma unroll
    for (int k = 0; k < K_; k++) {
        s[k] = __expf(fmaf(s[k], scale, -m));
        sum += s[k];
    }
    const float inv = 1.f / sum;

    // weighted feature gather: Ft16 row = 256 half = 32 uint4; lane ch 8L..8L+7
    float a[8] = {0.f, 0.f, 0.f, 0.f, 0.f, 0.f, 0.f, 0.f};
    const uint4* Fv = (const uint4*)g_Ft + (size_t)b * N_ * 32;
#pragma unroll
    for (int k = 0; k < K_; k++) {
        int j = __shfl_sync(0xffffffffu, jlane, k);
        float ak = s[k] * inv;
        uint4 f = Fv[(size_t)j * 32 + lane];
        float2 p0 = __half22float2(*(const __half2*)&f.x);
        float2 p1 = __half22float2(*(const __half2*)&f.y);
        float2 p2 = __half22float2(*(const __half2*)&f.z);
        float2 p3 = __half22float2(*(const __half2*)&f.w);
        a[0] = fmaf(ak, p0.x, a[0]); a[1] = fmaf(ak, p0.y, a[1]);
        a[2] = fmaf(ak, p1.x, a[2]); a[3] = fmaf(ak, p1.y, a[3]);
        a[4] = fmaf(ak, p2.x, a[4]); a[5] = fmaf(ak, p2.y, a[5]);
        a[6] = fmaf(ak, p3.x, a[6]); a[7] = fmaf(ak, p3.y, a[7]);
    }

    // stage [point][channel]; float2 stores, reads are 2-way-conflict max
    float* trow = &tile[w * 258 + 8 * lane];
#pragma unroll
    for (int i = 0; i < 4; i++)
        ((float2*)trow)[i] = make_float2(a[2 * i], a[2 * i + 1]);
    __syncthreads();

    // coalesced write: lanes sweep n, rows sweep c
    float* ob = out + (size_t)b * C_ * N_;
#pragma unroll
    for (int r = 0; r < 8; r++) {
        int c = w + r * 32;
        ob[(size_t)c * N_ + n0 + lane] = tile[lane * 258 + c];
    }
}

// ---------------- launch: forked graph (knn || prep), join before attn -------
extern "C" void kernel_launch(void* const* d_in, const int* in_sizes, int n_in,
                              void* d_out, int out_size) {
    (void)in_sizes; (void)n_in; (void)out_size;
    const float* xyz = (const float*)d_in[0];   // [B,N,3]
    const float* F   = (const float*)d_in[1];   // [B,C,N]
    const float* X   = (const float*)d_in[2];   // [B,N,D]
    const float* Wq  = (const float*)d_in[3];
    const float* bq  = (const float*)d_in[4];
    const float* Wk  = (const float*)d_in[5];
    float* out = (float*)d_out;                 // [B,C,N]

    // One-time host-side handles (no device memory; identical work every call).
    static cudaStream_t s2 = nullptr;
    static cudaEvent_t evF = nullptr, evJ = nullptr;
    if (s2 == nullptr) {
        cudaStreamCreateWithFlags(&s2, cudaStreamNonBlocking);
        cudaEventCreateWithFlags(&evF, cudaEventDisableTiming);
        cudaEventCreateWithFlags(&evJ, cudaEventDisableTiming);
        cudaFuncSetAttribute(knn_kernel, cudaFuncAttributeMaxDynamicSharedMemorySize, 65536);
    }

    // Fork: side stream s2 joins the (possibly capturing) main stream.
    cudaEventRecord(evF, 0);
    cudaStreamWaitEvent(s2, evF, 0);

    // Main-stream branch: knn (critical path, ~128us)
    knn_kernel<<<dim3(N_ / ((KNN_THREADS / 32) * QW_), B_), KNN_THREADS, 65536, 0>>>(xyz);

    // Side-stream branch: prep chain; qt co-resides with knn
    fold_kernel<<<D_, D_, 0, s2>>>(Wq, Wk, bq);
    transpose_kernel<<<dim3(N_ / 32, C_ / 32, B_), dim3(32, 8), 0, s2>>>(F);
    xhalf_kernel<<<(B_ * N_ * D_ / 4) / 256, 256, 0, s2>>>(X);
    qt_kernel<<<(B_ * N_) / 32, 256, 32768, s2>>>(X);

    // Join, then attention epilogue on the main stream.
    cudaEventRecord(evJ, s2);
    cudaStreamWaitEvent(0, evJ, 0);
    attn_kernel<<<dim3(N_ / 32, B_), 1024, 0, 0>>>(out);
}